// round 5
// baseline (speedup 1.0000x reference)
#include <cuda_runtime.h>

#define NN 100000
#define EE 1600000
#define CAPB 512   // edges cached in smem per block of 8 nodes (avg 128; P(>512)~0)

// ---------------- scratch (device globals; no allocation) ----------------
__device__ __align__(16) float g_hA[NN * 64];   // layer input  (edge kernel reads)
__device__ __align__(16) float g_hB[NN * 64];   // layer output (edge kernel writes)
__device__ float g_ssrc[NN * 2];
__device__ float g_sdst[NN * 2];
__device__ int   g_deg[NN];
__device__ int   g_rowptr[NN + 1];
__device__ int   g_cursor[NN];
__device__ int   g_col[EE];                     // packed: src | (cls<<20)

// ---------------- CSR build ----------------
__global__ void k_count_deg(const int* __restrict__ ei) {
    int e = blockIdx.x * blockDim.x + threadIdx.x;
    if (e < EE) atomicAdd(&g_deg[ei[EE + e]], 1);
}

// single-block scan: 1024 threads, each owns a contiguous chunk of 98 nodes
__global__ __launch_bounds__(1024) void k_scan() {
    __shared__ int part[1024];
    int t = threadIdx.x;
    const int CH = (NN + 1023) / 1024;  // 98
    int beg = t * CH;
    int end = beg + CH; if (end > NN) end = NN;
    int s = 0;
    for (int i = beg; i < end; i++) s += g_deg[i];
    part[t] = s;
    __syncthreads();
    for (int o = 1; o < 1024; o <<= 1) {
        int a = (t >= o) ? part[t - o] : 0;
        __syncthreads();
        part[t] += a;
        __syncthreads();
    }
    int run = part[t] - s;
    for (int i = beg; i < end; i++) {
        int d = g_deg[i];
        g_rowptr[i] = run;
        g_cursor[i] = run;
        run += d;
    }
    if (t == 1023) g_rowptr[NN] = EE;
}

// scatter edges into CSR + layer-0 fill (h = one_hot(n%4) @ W0 broadcast) + s tables
__global__ __launch_bounds__(256) void k_scatter_fill(const int* __restrict__ ei,
                                                      const int* __restrict__ ea,
                                                      const float* __restrict__ W0,
                                                      const float* __restrict__ asrc,
                                                      const float* __restrict__ adst) {
    __shared__ __align__(16) float w[256];
    __shared__ float tabs[8], tabd[8];
    int t = threadIdx.x;
    if (t < 256) w[t] = W0[t];
    __syncthreads();
    if (t < 8) {  // stab[label][h] = dot(W0[label, h*32:], att[0,h,:])
        int lab = t >> 1, h = t & 1;
        float ss = 0.f, sd = 0.f;
        for (int c = 0; c < 32; c++) {
            float hv = w[lab * 64 + h * 32 + c];
            ss = fmaf(hv, asrc[h * 32 + c], ss);
            sd = fmaf(hv, adst[h * 32 + c], sd);
        }
        tabs[t] = ss;
        tabd[t] = sd;
    }
    __syncthreads();

    int g = blockIdx.x * blockDim.x + t;
    int stride = gridDim.x * blockDim.x;

    // CSR scatter
    if (g < EE) {
        int s = ei[g];
        int d = ei[EE + g];
        int a = ea[g];
        int pos = atomicAdd(&g_cursor[d], 1);
        g_col[pos] = s | (a << 20);
    }

    // layer-0 h fill: NN*16 float4s
    float4* hA4 = (float4*)g_hA;
    const float4* w4 = (const float4*)w;
    for (int i = g; i < NN * 16; i += stride) {
        int n = i >> 4, q = i & 15;
        hA4[i] = w4[(n & 3) * 16 + q];
    }
    // s tables
    for (int i = g; i < NN * 2; i += stride) {
        int n = i >> 1, h = i & 1;
        g_ssrc[i] = tabs[(n & 3) * 2 + h];
        g_sdst[i] = tabd[(n & 3) * 2 + h];
    }
}

// ---------------- fused attention + aggregate + ELU ----------------
// Block = 8 nodes (contiguous edge range). Pass 1: all 256 threads edge-parallel.
// Pass 1b: per-warp denom reduce from smem. Pass 2: 2 edges x 16 lanes x float4.
__global__ __launch_bounds__(256) void k_edge(const float* __restrict__ eemb,
                                              const float* __restrict__ asrc,
                                              const float* __restrict__ bias, int l) {
    __shared__ __align__(16) float se[320];      // eemb[l]
    __shared__ float sesc[10];                   // escore[l][cls][h]
    __shared__ int   srow[9];
    __shared__ float2 ssd[8];
    __shared__ int   sp[CAPB];
    __shared__ float sex[2 * CAPB];

    int t = threadIdx.x;
    int n0 = blockIdx.x * 8;
    const float* el = eemb + l * 320;
    for (int i = t; i < 320; i += 256) se[i] = el[i];
    if (t < 9) srow[t] = g_rowptr[n0 + t];
    if (t < 8) ssd[t] = *(const float2*)&g_sdst[2 * (n0 + t)];
    __syncthreads();
    if (t < 10) {  // escore[cls][h] = dot(eemb[l,cls,h*32:], asrc[l,h,:])
        int cls = t >> 1, h = t & 1;
        float s = 0.f;
        for (int c = 0; c < 32; c++)
            s = fmaf(se[cls * 64 + h * 32 + c], asrc[l * 64 + h * 32 + c], s);
        sesc[t] = s;
    }
    __syncthreads();

    int ebeg = srow[0], eend = srow[8];
    int nblk = eend - ebeg;
    int ncap = nblk < CAPB ? nblk : CAPB;

    // pass 1: edge-parallel exp(logits) into smem (coalesced g_col, 256 gathers in flight)
    for (int off = t; off < ncap; off += 256) {
        int j = ebeg + off;
        int p = g_col[j];
        int src = p & 0xFFFFF, cls = p >> 20;
        int k = 0;
        #pragma unroll
        for (int i = 1; i < 8; i++) k += (j >= srow[i]);
        float2 sd = ssd[k];
        float2 ss = *(const float2*)&g_ssrc[2 * src];
        float l0 = sd.x + ss.x + sesc[cls * 2];
        float l1 = sd.y + ss.y + sesc[cls * 2 + 1];
        l0 = l0 > 0.f ? l0 : 0.2f * l0;
        l1 = l1 > 0.f ? l1 : 0.2f * l1;
        sp[off] = p;
        sex[2 * off]     = __expf(l0);
        sex[2 * off + 1] = __expf(l1);
    }
    __syncthreads();

    // pass 1b: per-warp denominator reduce (deterministic lane order)
    int warp = t >> 5, lane = t & 31;
    int beg = srow[warp], end = srow[warp + 1];
    float2 sdn = ssd[warp];
    float d0 = 0.f, d1 = 0.f;
    for (int j = beg + lane; j < end; j += 32) {
        int off = j - ebeg;
        float e0, e1;
        if (off < CAPB) {
            e0 = sex[2 * off];
            e1 = sex[2 * off + 1];
        } else {  // astronomically rare overflow: recompute
            int p = g_col[j];
            int src = p & 0xFFFFF, cls = p >> 20;
            float2 ss = *(const float2*)&g_ssrc[2 * src];
            float l0 = sdn.x + ss.x + sesc[cls * 2];
            float l1 = sdn.y + ss.y + sesc[cls * 2 + 1];
            l0 = l0 > 0.f ? l0 : 0.2f * l0;
            l1 = l1 > 0.f ? l1 : 0.2f * l1;
            e0 = __expf(l0);
            e1 = __expf(l1);
        }
        d0 += e0;
        d1 += e1;
    }
    #pragma unroll
    for (int o = 16; o; o >>= 1) {
        d0 += __shfl_xor_sync(0xffffffffu, d0, o);
        d1 += __shfl_xor_sync(0xffffffffu, d1, o);
    }
    float inv0 = 1.f / (d0 + 1e-16f), inv1 = 1.f / (d1 + 1e-16f);

    // pass 2: acc = sum ex*(h[src]+e[cls]); 2 edges x 16 lanes x float4
    int half = lane >> 4;
    int qlane = lane & 15;
    int ch4 = qlane * 4;
    int hs = qlane >> 3;
    float inv = hs ? inv1 : inv0;
    float4 acc = make_float4(0.f, 0.f, 0.f, 0.f);

    int m = end - beg;
    int boff = beg - ebeg;
    #pragma unroll 2
    for (int base = 0; base < m; base += 2) {
        int idx = base + half;
        float ex = 0.f;
        int p = 0;
        if (idx < m) {
            int off = boff + idx;
            if (off < CAPB) {
                p = sp[off];
                ex = sex[2 * off + hs];
            } else {  // rare overflow: recompute
                p = g_col[beg + idx];
                int src = p & 0xFFFFF, cls = p >> 20;
                float ssh = g_ssrc[2 * src + hs];
                float sdh = hs ? sdn.y : sdn.x;
                float lh = sdh + ssh + sesc[cls * 2 + hs];
                lh = lh > 0.f ? lh : 0.2f * lh;
                ex = __expf(lh);
            }
        }
        int src = p & 0xFFFFF, cls = p >> 20;
        float4 hv = *(const float4*)&g_hA[src * 64 + ch4];
        float4 ev = *(const float4*)&se[cls * 64 + ch4];
        acc.x = fmaf(ex, hv.x + ev.x, acc.x);
        acc.y = fmaf(ex, hv.y + ev.y, acc.y);
        acc.z = fmaf(ex, hv.z + ev.z, acc.z);
        acc.w = fmaf(ex, hv.w + ev.w, acc.w);
    }

    // combine the two edge-parity halves (paired lanes share qlane)
    acc.x += __shfl_xor_sync(0xffffffffu, acc.x, 16);
    acc.y += __shfl_xor_sync(0xffffffffu, acc.y, 16);
    acc.z += __shfl_xor_sync(0xffffffffu, acc.z, 16);
    acc.w += __shfl_xor_sync(0xffffffffu, acc.w, 16);

    if (half == 0) {
        int n = n0 + warp;
        const float* b = bias + l * 64 + ch4;
        float4 o;
        o.x = fmaf(acc.x, inv, b[0]);
        o.y = fmaf(acc.y, inv, b[1]);
        o.z = fmaf(acc.z, inv, b[2]);
        o.w = fmaf(acc.w, inv, b[3]);
        o.x = o.x > 0.f ? o.x : expm1f(o.x);
        o.y = o.y > 0.f ? o.y : expm1f(o.y);
        o.z = o.z > 0.f ? o.z : expm1f(o.z);
        o.w = o.w > 0.f ? o.w : expm1f(o.w);
        *(float4*)&g_hB[n * 64 + ch4] = o;
    }
}

// ---------------- 64x64 GEMM: hA = hB @ W13[l-1], plus s_src/s_dst ----------------
__global__ __launch_bounds__(256) void k_gemm(const float* __restrict__ W13,
                                              const float* __restrict__ asrc,
                                              const float* __restrict__ adst, int l) {
    __shared__ __align__(16) float4 Ws4[1024];  // W[k][j] as float4 over j (16KB)
    __shared__ float Hs[128 * 33];
    __shared__ float Av[64], Dv[64];

    int t = threadIdx.x;
    float* Wsf = (float*)Ws4;
    const float* W = W13 + (l - 1) * 4096;
    for (int i = t; i < 4096; i += 256) Wsf[i] = W[i];
    if (t < 64) { Av[t] = asrc[l * 64 + t]; Dv[t] = adst[l * 64 + t]; }

    int base = blockIdx.x * 128;
    int rows = NN - base; if (rows > 128) rows = 128;
    int node_l = t >> 1, h = t & 1;

    float acc[32];
    #pragma unroll
    for (int j = 0; j < 32; j++) acc[j] = 0.f;

    for (int ph = 0; ph < 2; ph++) {
        __syncthreads();
        for (int i = t; i < rows * 32; i += 256) {
            int r = i >> 5, kk = i & 31;
            Hs[r * 33 + kk] = g_hB[(base + r) * 64 + ph * 32 + kk];
        }
        __syncthreads();
        if (node_l < rows) {
            #pragma unroll 4
            for (int kk = 0; kk < 32; kk++) {
                float rk = Hs[node_l * 33 + kk];
                int k = ph * 32 + kk;
                const float4* wr = &Ws4[k * 16 + h * 8];
                #pragma unroll
                for (int j4 = 0; j4 < 8; j4++) {
                    float4 w = wr[j4];
                    acc[4 * j4 + 0] = fmaf(rk, w.x, acc[4 * j4 + 0]);
                    acc[4 * j4 + 1] = fmaf(rk, w.y, acc[4 * j4 + 1]);
                    acc[4 * j4 + 2] = fmaf(rk, w.z, acc[4 * j4 + 2]);
                    acc[4 * j4 + 3] = fmaf(rk, w.w, acc[4 * j4 + 3]);
                }
            }
        }
    }

    if (node_l < rows) {
        int n = base + node_l;
        float ss = 0.f, sdd = 0.f;
        #pragma unroll
        for (int j = 0; j < 32; j++) {
            ss  = fmaf(acc[j], Av[h * 32 + j], ss);
            sdd = fmaf(acc[j], Dv[h * 32 + j], sdd);
        }
        float4* op = (float4*)&g_hA[n * 64 + h * 32];
        #pragma unroll
        for (int j4 = 0; j4 < 8; j4++)
            op[j4] = make_float4(acc[4 * j4], acc[4 * j4 + 1], acc[4 * j4 + 2], acc[4 * j4 + 3]);
        g_ssrc[2 * n + h] = ss;
        g_sdst[2 * n + h] = sdd;
    }
}

// ---------------- MF decoder: out[i] = dot(h[4i], h[4i+1]) ----------------
__global__ void k_decode(float* __restrict__ out) {
    int t = threadIdx.x, warp = t >> 5, lane = t & 31;
    int i = blockIdx.x * 8 + warp;
    if (i >= 25000) return;
    const float2* u = (const float2*)&g_hB[(4 * i) * 64];
    const float2* v = (const float2*)&g_hB[(4 * i + 1) * 64];
    float2 a = u[lane], b = v[lane];
    float s = a.x * b.x + a.y * b.y;
    #pragma unroll
    for (int o = 16; o; o >>= 1) s += __shfl_xor_sync(0xffffffffu, s, o);
    if (lane == 0) out[i] = s;
}

// ---------------- launch ----------------
extern "C" void kernel_launch(void* const* d_in, const int* in_sizes, int n_in,
                              void* d_out, int out_size) {
    const float* W0   = (const float*)d_in[1];
    const float* W13  = (const float*)d_in[2];
    const float* eemb = (const float*)d_in[3];
    const float* asrc = (const float*)d_in[4];
    const float* adst = (const float*)d_in[5];
    const float* bias = (const float*)d_in[6];
    const int*   ei   = (const int*)d_in[7];
    const int*   ea   = (const int*)d_in[8];
    float* out = (float*)d_out;

    void* degp;
    cudaGetSymbolAddress(&degp, g_deg);
    cudaMemsetAsync(degp, 0, NN * sizeof(int));

    k_count_deg<<<(EE + 255) / 256, 256>>>(ei);                     // launch 1
    k_scan<<<1, 1024>>>();                                          // launch 2
    k_scatter_fill<<<(EE + 255) / 256, 256>>>(ei, ea, W0, asrc, adst); // launch 3
    k_edge<<<NN / 8, 256>>>(eemb, asrc, bias, 0);                   // launch 4 <- profiled
    for (int l = 1; l < 4; l++) {
        k_gemm<<<(NN + 127) / 128, 256>>>(W13, asrc, adst, l);
        k_edge<<<NN / 8, 256>>>(eemb, asrc, bias, l);
    }
    k_decode<<<(25000 + 7) / 8, 256>>>(out);
}

// round 6
// speedup vs baseline: 1.4617x; 1.4617x over previous
#include <cuda_runtime.h>

#define NN 100000
#define EE 1600000

// ---------------- scratch (device globals; no allocation) ----------------
__device__ __align__(16) float g_hA[NN * 64];   // layer input  (edge kernel reads)
__device__ __align__(16) float g_hB[NN * 64];   // layer output (edge kernel writes)
__device__ float g_ssrc[NN * 2];
__device__ float g_sdst[NN * 2];
__device__ int   g_deg[NN];
__device__ int   g_beg[NN];
__device__ int   g_cursor[NN];
__device__ int   g_col[EE];                     // packed: src | (cls<<20)
__device__ int   g_ticket;
__device__ float2 g_escore[20];                 // [l*5+cls] = (score_h0, score_h1)

// ---------------- CSR: degree count ----------------
__global__ void k_count_deg(const int* __restrict__ ei) {
    int e = blockIdx.x * blockDim.x + threadIdx.x;
    if (e < EE) atomicAdd(&g_deg[ei[EE + e]], 1);
}

// ---------------- CSR: order-free scan (atomic ticket per block) ----------------
// CSR only needs DISJOINT per-node ranges, not index-ordered ones.
__global__ __launch_bounds__(1024) void k_scan(const int* __restrict__ ei) {
    __shared__ int sh[1024];
    __shared__ int sbase;
    int t = threadIdx.x;
    int i = blockIdx.x * 1024 + t;
    int v = (i < NN) ? g_deg[i] : 0;
    sh[t] = v;
    __syncthreads();
    for (int o = 1; o < 1024; o <<= 1) {
        int a = (t >= o) ? sh[t - o] : 0;
        __syncthreads();
        sh[t] += a;
        __syncthreads();
    }
    if (t == 1023) sbase = atomicAdd(&g_ticket, sh[1023]);
    __syncthreads();
    if (i < NN) {
        int b = sbase + sh[t] - v;  // block-exclusive prefix + block base
        g_beg[i] = b;
        g_cursor[i] = b;
    }
}

// ---------------- CSR scatter + layer-0 fill + tables ----------------
__global__ __launch_bounds__(256) void k_scatter_fill(const int* __restrict__ ei,
                                                      const int* __restrict__ ea,
                                                      const float* __restrict__ W0,
                                                      const float* __restrict__ eemb,
                                                      const float* __restrict__ asrc,
                                                      const float* __restrict__ adst) {
    __shared__ __align__(16) float w[256];
    __shared__ float tabs[8], tabd[8];
    int t = threadIdx.x;
    if (t < 256) w[t] = W0[t];
    __syncthreads();
    if (t < 8) {  // layer-0 s tables: stab[label][h] = dot(W0[label,h*32:], att[0,h,:])
        int lab = t >> 1, h = t & 1;
        float ss = 0.f, sd = 0.f;
        for (int c = 0; c < 32; c++) {
            float hv = w[lab * 64 + h * 32 + c];
            ss = fmaf(hv, asrc[h * 32 + c], ss);
            sd = fmaf(hv, adst[h * 32 + c], sd);
        }
        tabs[t] = ss;
        tabd[t] = sd;
    }
    __syncthreads();
    // escore[l][cls][h] = dot(eemb[l,cls,h*32:], asrc[l,h,:])  (block 0 only)
    if (blockIdx.x == 0 && t < 20) {
        int l = t / 5, cls = t % 5;
        float2 s = make_float2(0.f, 0.f);
        for (int c = 0; c < 32; c++) {
            s.x = fmaf(eemb[l * 320 + cls * 64 + c],      asrc[l * 64 + c],      s.x);
            s.y = fmaf(eemb[l * 320 + cls * 64 + 32 + c], asrc[l * 64 + 32 + c], s.y);
        }
        g_escore[t] = s;
    }

    int g = blockIdx.x * blockDim.x + t;
    int stride = gridDim.x * blockDim.x;

    // CSR scatter
    if (g < EE) {
        int s = ei[g];
        int d = ei[EE + g];
        int a = ea[g];
        int pos = atomicAdd(&g_cursor[d], 1);
        g_col[pos] = s | (a << 20);
    }

    // layer-0 h fill: h[n,:] = W0[n%4,:]
    float4* hA4 = (float4*)g_hA;
    const float4* w4 = (const float4*)w;
    for (int i = g; i < NN * 16; i += stride) {
        int n = i >> 4, q = i & 15;
        hA4[i] = w4[(n & 3) * 16 + q];
    }
    for (int i = g; i < NN * 2; i += stride) {
        int n = i >> 1, h = i & 1;
        g_ssrc[i] = tabs[(n & 3) * 2 + h];
        g_sdst[i] = tabd[(n & 3) * 2 + h];
    }
}

// ---------------- fused attention + aggregate + ELU ----------------
// Warp per node. Pass 1: lane = edge, (p, e0, e1) stay in REGISTERS.
// Pass 2: 2 edges x 16 lanes x float4; edge data via SHFL.IDX (no smem staging).
__global__ __launch_bounds__(256) void k_edge(const float* __restrict__ eemb,
                                              const float* __restrict__ bias, int l) {
    __shared__ __align__(16) float se[320];   // eemb[l]
    __shared__ float2 sesc[5];                // escore[l]

    int t = threadIdx.x;
    const float* el = eemb + l * 320;
    for (int i = t; i < 320; i += 256) se[i] = el[i];
    if (t < 5) sesc[t] = g_escore[l * 5 + t];
    __syncthreads();

    int warp = t >> 5, lane = t & 31;
    int n = blockIdx.x * 8 + warp;              // grid = NN/8 exactly

    int beg = g_beg[n];
    int deg = g_deg[n];
    float2 sd = *(const float2*)&g_sdst[2 * n];

    // ---- pass 1: first 32 edges in registers ----
    int p = 0;
    float e0 = 0.f, e1 = 0.f;
    if (lane < deg) {
        p = g_col[beg + lane];
        int src = p & 0xFFFFF, cls = p >> 20;
        float2 ss = *(const float2*)&g_ssrc[2 * src];
        float2 esc = sesc[cls];
        float l0 = (sd.x + ss.x) + esc.x;
        float l1 = (sd.y + ss.y) + esc.y;
        l0 = fmaxf(l0, 0.2f * l0);              // leaky_relu(x,0.2)
        l1 = fmaxf(l1, 0.2f * l1);
        e0 = __expf(l0);
        e1 = __expf(l1);
    }
    float d0 = e0, d1 = e1;
    for (int j = beg + 32 + lane; j < beg + deg; j += 32) {  // rare deg>32 tail
        int pp = g_col[j];
        int src = pp & 0xFFFFF, cls = pp >> 20;
        float2 ss = *(const float2*)&g_ssrc[2 * src];
        float2 esc = sesc[cls];
        float l0 = (sd.x + ss.x) + esc.x;
        float l1 = (sd.y + ss.y) + esc.y;
        l0 = fmaxf(l0, 0.2f * l0);
        l1 = fmaxf(l1, 0.2f * l1);
        d0 += __expf(l0);
        d1 += __expf(l1);
    }
    #pragma unroll
    for (int o = 16; o; o >>= 1) {
        d0 += __shfl_xor_sync(0xffffffffu, d0, o);
        d1 += __shfl_xor_sync(0xffffffffu, d1, o);
    }
    float inv0 = 1.f / (d0 + 1e-16f), inv1 = 1.f / (d1 + 1e-16f);

    // ---- pass 2: acc = sum ex*(h[src]+e[cls]) ----
    int half = lane >> 4;      // edge parity within a pair
    int q = lane & 15;         // channel quad
    int ch4 = q * 4;
    int hs = q >> 3;           // head of my channels
    float inv = hs ? inv1 : inv0;
    float4 accA = make_float4(0.f, 0.f, 0.f, 0.f);
    float4 accB = make_float4(0.f, 0.f, 0.f, 0.f);

    int m = deg < 32 ? deg : 32;
    for (int base = 0; base < m; base += 4) {
        int iA = base + half;            // edges base..base+1
        int iB = base + 2 + half;        // edges base+2..base+3 (max 31)
        int pA = __shfl_sync(0xffffffffu, p, iA);
        int pB = __shfl_sync(0xffffffffu, p, iB);
        float a0 = __shfl_sync(0xffffffffu, e0, iA);
        float a1 = __shfl_sync(0xffffffffu, e1, iA);
        float b0 = __shfl_sync(0xffffffffu, e0, iB);
        float b1 = __shfl_sync(0xffffffffu, e1, iB);
        float exA = hs ? a1 : a0;        // inactive-lane e == 0 -> contributes 0
        float exB = hs ? b1 : b0;
        int sA = pA & 0xFFFFF, cA = pA >> 20;
        int sB = pB & 0xFFFFF, cB = pB >> 20;
        float4 hvA = *(const float4*)&g_hA[sA * 64 + ch4];
        float4 hvB = *(const float4*)&g_hA[sB * 64 + ch4];
        float4 evA = *(const float4*)&se[cA * 64 + ch4];
        float4 evB = *(const float4*)&se[cB * 64 + ch4];
        accA.x = fmaf(exA, hvA.x + evA.x, accA.x);
        accA.y = fmaf(exA, hvA.y + evA.y, accA.y);
        accA.z = fmaf(exA, hvA.z + evA.z, accA.z);
        accA.w = fmaf(exA, hvA.w + evA.w, accA.w);
        accB.x = fmaf(exB, hvB.x + evB.x, accB.x);
        accB.y = fmaf(exB, hvB.y + evB.y, accB.y);
        accB.z = fmaf(exB, hvB.z + evB.z, accB.z);
        accB.w = fmaf(exB, hvB.w + evB.w, accB.w);
    }
    for (int j = beg + 32; j < beg + deg; j += 2) {  // rare deg>32 tail: recompute ex
        int idx = j + half;
        float ex = 0.f;
        int pp = 0;
        if (idx < beg + deg) {
            pp = g_col[idx];
            int src = pp & 0xFFFFF, cls = pp >> 20;
            float ssh = g_ssrc[2 * src + hs];
            float sdh = hs ? sd.y : sd.x;
            float ech = hs ? sesc[cls].y : sesc[cls].x;
            float lh = sdh + ssh + ech;
            lh = fmaxf(lh, 0.2f * lh);
            ex = __expf(lh);
        }
        int src = pp & 0xFFFFF, cls = pp >> 20;
        float4 hv = *(const float4*)&g_hA[src * 64 + ch4];
        float4 ev = *(const float4*)&se[cls * 64 + ch4];
        accA.x = fmaf(ex, hv.x + ev.x, accA.x);
        accA.y = fmaf(ex, hv.y + ev.y, accA.y);
        accA.z = fmaf(ex, hv.z + ev.z, accA.z);
        accA.w = fmaf(ex, hv.w + ev.w, accA.w);
    }

    accA.x += accB.x; accA.y += accB.y; accA.z += accB.z; accA.w += accB.w;
    accA.x += __shfl_xor_sync(0xffffffffu, accA.x, 16);
    accA.y += __shfl_xor_sync(0xffffffffu, accA.y, 16);
    accA.z += __shfl_xor_sync(0xffffffffu, accA.z, 16);
    accA.w += __shfl_xor_sync(0xffffffffu, accA.w, 16);

    if (half == 0) {
        const float* b = bias + l * 64 + ch4;
        float4 o;
        o.x = fmaf(accA.x, inv, b[0]);
        o.y = fmaf(accA.y, inv, b[1]);
        o.z = fmaf(accA.z, inv, b[2]);
        o.w = fmaf(accA.w, inv, b[3]);
        o.x = o.x > 0.f ? o.x : expm1f(o.x);
        o.y = o.y > 0.f ? o.y : expm1f(o.y);
        o.z = o.z > 0.f ? o.z : expm1f(o.z);
        o.w = o.w > 0.f ? o.w : expm1f(o.w);
        *(float4*)&g_hB[n * 64 + ch4] = o;
    }
}

// ---------------- 64x64 GEMM: hA = hB @ W13[l-1], plus s_src/s_dst ----------------
__global__ __launch_bounds__(256) void k_gemm(const float* __restrict__ W13,
                                              const float* __restrict__ asrc,
                                              const float* __restrict__ adst, int l) {
    __shared__ __align__(16) float4 Ws4[1024];  // W[k][j] as float4 over j (16KB)
    __shared__ float Hs[128 * 33];
    __shared__ float Av[64], Dv[64];

    int t = threadIdx.x;
    float* Wsf = (float*)Ws4;
    const float* W = W13 + (l - 1) * 4096;
    for (int i = t; i < 4096; i += 256) Wsf[i] = W[i];
    if (t < 64) { Av[t] = asrc[l * 64 + t]; Dv[t] = adst[l * 64 + t]; }

    int base = blockIdx.x * 128;
    int rows = NN - base; if (rows > 128) rows = 128;
    int node_l = t >> 1, h = t & 1;

    float acc[32];
    #pragma unroll
    for (int j = 0; j < 32; j++) acc[j] = 0.f;

    for (int ph = 0; ph < 2; ph++) {
        __syncthreads();
        for (int i = t; i < rows * 32; i += 256) {
            int r = i >> 5, kk = i & 31;
            Hs[r * 33 + kk] = g_hB[(base + r) * 64 + ph * 32 + kk];
        }
        __syncthreads();
        if (node_l < rows) {
            #pragma unroll 4
            for (int kk = 0; kk < 32; kk++) {
                float rk = Hs[node_l * 33 + kk];
                int k = ph * 32 + kk;
                const float4* wr = &Ws4[k * 16 + h * 8];
                #pragma unroll
                for (int j4 = 0; j4 < 8; j4++) {
                    float4 w = wr[j4];
                    acc[4 * j4 + 0] = fmaf(rk, w.x, acc[4 * j4 + 0]);
                    acc[4 * j4 + 1] = fmaf(rk, w.y, acc[4 * j4 + 1]);
                    acc[4 * j4 + 2] = fmaf(rk, w.z, acc[4 * j4 + 2]);
                    acc[4 * j4 + 3] = fmaf(rk, w.w, acc[4 * j4 + 3]);
                }
            }
        }
    }

    if (node_l < rows) {
        int n = base + node_l;
        float ss = 0.f, sdd = 0.f;
        #pragma unroll
        for (int j = 0; j < 32; j++) {
            ss  = fmaf(acc[j], Av[h * 32 + j], ss);
            sdd = fmaf(acc[j], Dv[h * 32 + j], sdd);
        }
        float4* op = (float4*)&g_hA[n * 64 + h * 32];
        #pragma unroll
        for (int j4 = 0; j4 < 8; j4++)
            op[j4] = make_float4(acc[4 * j4], acc[4 * j4 + 1], acc[4 * j4 + 2], acc[4 * j4 + 3]);
        g_ssrc[2 * n + h] = ss;
        g_sdst[2 * n + h] = sdd;
    }
}

// ---------------- MF decoder: out[i] = dot(h[4i], h[4i+1]) ----------------
__global__ void k_decode(float* __restrict__ out) {
    int t = threadIdx.x, warp = t >> 5, lane = t & 31;
    int i = blockIdx.x * 8 + warp;
    if (i >= 25000) return;
    const float2* u = (const float2*)&g_hB[(4 * i) * 64];
    const float2* v = (const float2*)&g_hB[(4 * i + 1) * 64];
    float2 a = u[lane], b = v[lane];
    float s = a.x * b.x + a.y * b.y;
    #pragma unroll
    for (int o = 16; o; o >>= 1) s += __shfl_xor_sync(0xffffffffu, s, o);
    if (lane == 0) out[i] = s;
}

// ---------------- launch ----------------
extern "C" void kernel_launch(void* const* d_in, const int* in_sizes, int n_in,
                              void* d_out, int out_size) {
    const float* W0   = (const float*)d_in[1];
    const float* W13  = (const float*)d_in[2];
    const float* eemb = (const float*)d_in[3];
    const float* asrc = (const float*)d_in[4];
    const float* adst = (const float*)d_in[5];
    const float* bias = (const float*)d_in[6];
    const int*   ei   = (const int*)d_in[7];
    const int*   ea   = (const int*)d_in[8];
    float* out = (float*)d_out;

    void* degp; cudaGetSymbolAddress(&degp, g_deg);
    void* tickp; cudaGetSymbolAddress(&tickp, g_ticket);
    cudaMemsetAsync(degp, 0, NN * sizeof(int));
    cudaMemsetAsync(tickp, 0, sizeof(int));

    k_count_deg<<<(EE + 255) / 256, 256>>>(ei);                          // launch 1
    k_scan<<<(NN + 1023) / 1024, 1024>>>(ei);                            // launch 2
    k_scatter_fill<<<(EE + 255) / 256, 256>>>(ei, ea, W0, eemb, asrc, adst); // launch 3
    k_edge<<<NN / 8, 256>>>(eemb, bias, 0);                              // launch 4 <- profiled
    for (int l = 1; l < 4; l++) {
        k_gemm<<<(NN + 127) / 128, 256>>>(W13, asrc, adst, l);
        k_edge<<<NN / 8, 256>>>(eemb, bias, l);
    }
    k_decode<<<(25000 + 7) / 8, 256>>>(out);
}

// round 7
// speedup vs baseline: 1.5904x; 1.0881x over previous
#include <cuda_runtime.h>

#define NN 100000
#define EE 1600000
typedef unsigned long long ull;

struct __align__(16) ULL2 { ull a, b; };

__device__ __forceinline__ ull pk2(float x, float y) {
    ull r; asm("mov.b64 %0, {%1,%2};" : "=l"(r) : "f"(x), "f"(y)); return r;
}
__device__ __forceinline__ float2 upk2(ull a) {
    float2 v; asm("mov.b64 {%0,%1}, %2;" : "=f"(v.x), "=f"(v.y) : "l"(a)); return v;
}
__device__ __forceinline__ ull fma2(ull a, ull b, ull c) {
    ull d; asm("fma.rn.f32x2 %0, %1, %2, %3;" : "=l"(d) : "l"(a), "l"(b), "l"(c)); return d;
}

// ---------------- scratch (device globals; no allocation) ----------------
__device__ __align__(16) float g_hA[NN * 64];   // layer input  (edge kernel reads)
__device__ __align__(16) float g_hB[NN * 64];   // layer output (edge kernel writes)
__device__ float g_ssrc[NN * 2];
__device__ float g_sdst[NN * 2];
__device__ int2  g_range[NN];                   // (beg, deg)
__device__ int   g_deg[NN];
__device__ int   g_cursor[NN];
__device__ int   g_col[EE];                     // packed: src*64 | (cls<<23)
__device__ int   g_ticket;
__device__ float2 g_escore[20];                 // [l*5+cls] = (score_h0, score_h1)

// ---------------- CSR: degree count ----------------
__global__ void k_count_deg(const int* __restrict__ ei) {
    int e = blockIdx.x * blockDim.x + threadIdx.x;
    if (e < EE) atomicAdd(&g_deg[ei[EE + e]], 1);
}

// ---------------- CSR: order-free scan (atomic ticket per block) ----------------
__global__ __launch_bounds__(1024) void k_scan() {
    __shared__ int sh[1024];
    __shared__ int sbase;
    int t = threadIdx.x;
    int i = blockIdx.x * 1024 + t;
    int v = (i < NN) ? g_deg[i] : 0;
    sh[t] = v;
    __syncthreads();
    for (int o = 1; o < 1024; o <<= 1) {
        int a = (t >= o) ? sh[t - o] : 0;
        __syncthreads();
        sh[t] += a;
        __syncthreads();
    }
    if (t == 1023) sbase = atomicAdd(&g_ticket, sh[1023]);
    __syncthreads();
    if (i < NN) {
        int b = sbase + sh[t] - v;
        g_range[i] = make_int2(b, v);
        g_cursor[i] = b;
    }
}

// ---------------- CSR scatter + layer-0 fill + tables ----------------
__global__ __launch_bounds__(256) void k_scatter_fill(const int* __restrict__ ei,
                                                      const int* __restrict__ ea,
                                                      const float* __restrict__ W0,
                                                      const float* __restrict__ eemb,
                                                      const float* __restrict__ asrc,
                                                      const float* __restrict__ adst) {
    __shared__ __align__(16) float w[256];
    __shared__ float tabs[8], tabd[8];
    int t = threadIdx.x;
    if (t < 256) w[t] = W0[t];
    __syncthreads();
    if (t < 8) {  // layer-0 s tables
        int lab = t >> 1, h = t & 1;
        float ss = 0.f, sd = 0.f;
        for (int c = 0; c < 32; c++) {
            float hv = w[lab * 64 + h * 32 + c];
            ss = fmaf(hv, asrc[h * 32 + c], ss);
            sd = fmaf(hv, adst[h * 32 + c], sd);
        }
        tabs[t] = ss;
        tabd[t] = sd;
    }
    __syncthreads();
    if (blockIdx.x == 0 && t < 20) {  // escore tables
        int l = t / 5, cls = t % 5;
        float2 s = make_float2(0.f, 0.f);
        for (int c = 0; c < 32; c++) {
            s.x = fmaf(eemb[l * 320 + cls * 64 + c],      asrc[l * 64 + c],      s.x);
            s.y = fmaf(eemb[l * 320 + cls * 64 + 32 + c], asrc[l * 64 + 32 + c], s.y);
        }
        g_escore[t] = s;
    }

    int g = blockIdx.x * blockDim.x + t;
    int stride = gridDim.x * blockDim.x;

    if (g < EE) {
        int s = ei[g];
        int d = ei[EE + g];
        int a = ea[g];
        int pos = atomicAdd(&g_cursor[d], 1);
        g_col[pos] = (s << 6) | (a << 23);   // src*64 | cls<<23
    }

    float4* hA4 = (float4*)g_hA;
    const float4* w4 = (const float4*)w;
    for (int i = g; i < NN * 16; i += stride) {
        int n = i >> 4, q = i & 15;
        hA4[i] = w4[(n & 3) * 16 + q];
    }
    for (int i = g; i < NN * 2; i += stride) {
        int n = i >> 1, h = i & 1;
        g_ssrc[i] = tabs[(n & 3) * 2 + h];
        g_sdst[i] = tabd[(n & 3) * 2 + h];
    }
}

// ---------------- fused attention + aggregate + ELU ----------------
// Warp per node; (p, e0, e1) register-resident; pass 2 via SHFL.IDX.
__global__ __launch_bounds__(256) void k_edge(const float* __restrict__ eemb,
                                              const float* __restrict__ bias, int l) {
    __shared__ __align__(16) float se[320];   // eemb[l]
    __shared__ float2 sesc[5];                // escore[l]

    int t = threadIdx.x;
    const float* el = eemb + l * 320;
    for (int i = t; i < 320; i += 256) se[i] = el[i];
    if (t < 5) sesc[t] = g_escore[l * 5 + t];
    __syncthreads();

    int warp = t >> 5, lane = t & 31;
    int n = blockIdx.x * 8 + warp;

    int2 rng = g_range[n];
    int beg = rng.x, deg = rng.y;
    float2 sd = *(const float2*)&g_sdst[2 * n];

    // ---- pass 1: first 32 edges in registers ----
    int p = 0;
    float e0 = 0.f, e1 = 0.f;
    if (lane < deg) {
        p = g_col[beg + lane];
        int src = (p & 0x7FFFFF) >> 6, cls = p >> 23;
        float2 ss = *(const float2*)&g_ssrc[2 * src];
        float2 esc = sesc[cls];
        float l0 = (sd.x + ss.x) + esc.x;
        float l1 = (sd.y + ss.y) + esc.y;
        l0 = fmaxf(l0, 0.2f * l0);
        l1 = fmaxf(l1, 0.2f * l1);
        e0 = __expf(l0);
        e1 = __expf(l1);
    }
    float d0 = e0, d1 = e1;
    for (int j = beg + 32 + lane; j < beg + deg; j += 32) {  // rare deg>32 tail
        int pp = g_col[j];
        int src = (pp & 0x7FFFFF) >> 6, cls = pp >> 23;
        float2 ss = *(const float2*)&g_ssrc[2 * src];
        float2 esc = sesc[cls];
        float l0 = (sd.x + ss.x) + esc.x;
        float l1 = (sd.y + ss.y) + esc.y;
        l0 = fmaxf(l0, 0.2f * l0);
        l1 = fmaxf(l1, 0.2f * l1);
        d0 += __expf(l0);
        d1 += __expf(l1);
    }
    #pragma unroll
    for (int o = 16; o; o >>= 1) {
        d0 += __shfl_xor_sync(0xffffffffu, d0, o);
        d1 += __shfl_xor_sync(0xffffffffu, d1, o);
    }
    float inv0 = 1.f / (d0 + 1e-16f), inv1 = 1.f / (d1 + 1e-16f);

    // ---- pass 2 ----
    int half = lane >> 4;
    int q = lane & 15;
    int ch4 = q * 4;
    int hs = q >> 3;
    float inv = hs ? inv1 : inv0;
    float4 accA = make_float4(0.f, 0.f, 0.f, 0.f);
    float4 accB = make_float4(0.f, 0.f, 0.f, 0.f);

    int m = deg < 32 ? deg : 32;
    for (int base = 0; base < m; base += 4) {
        int iA = base + half;
        int iB = base + 2 + half;
        int pA = __shfl_sync(0xffffffffu, p, iA);
        int pB = __shfl_sync(0xffffffffu, p, iB);
        float a0 = __shfl_sync(0xffffffffu, e0, iA);
        float a1 = __shfl_sync(0xffffffffu, e1, iA);
        float b0 = __shfl_sync(0xffffffffu, e0, iB);
        float b1 = __shfl_sync(0xffffffffu, e1, iB);
        float exA = hs ? a1 : a0;
        float exB = hs ? b1 : b0;
        int aA = (pA & 0x7FFFFF) + ch4, cA = pA >> 23;
        int aB = (pB & 0x7FFFFF) + ch4, cB = pB >> 23;
        float4 hvA = *(const float4*)&g_hA[aA];
        float4 hvB = *(const float4*)&g_hA[aB];
        float4 evA = *(const float4*)&se[cA * 64 + ch4];
        float4 evB = *(const float4*)&se[cB * 64 + ch4];
        accA.x = fmaf(exA, hvA.x + evA.x, accA.x);
        accA.y = fmaf(exA, hvA.y + evA.y, accA.y);
        accA.z = fmaf(exA, hvA.z + evA.z, accA.z);
        accA.w = fmaf(exA, hvA.w + evA.w, accA.w);
        accB.x = fmaf(exB, hvB.x + evB.x, accB.x);
        accB.y = fmaf(exB, hvB.y + evB.y, accB.y);
        accB.z = fmaf(exB, hvB.z + evB.z, accB.z);
        accB.w = fmaf(exB, hvB.w + evB.w, accB.w);
    }
    for (int j = beg + 32; j < beg + deg; j += 2) {  // rare deg>32 tail
        int idx = j + half;
        float ex = 0.f;
        int pp = 0;
        if (idx < beg + deg) {
            pp = g_col[idx];
            int src = (pp & 0x7FFFFF) >> 6, cls = pp >> 23;
            float ssh = g_ssrc[2 * src + hs];
            float sdh = hs ? sd.y : sd.x;
            float ech = hs ? sesc[cls].y : sesc[cls].x;
            float lh = sdh + ssh + ech;
            lh = fmaxf(lh, 0.2f * lh);
            ex = __expf(lh);
        }
        int aa = (pp & 0x7FFFFF) + ch4, cls = pp >> 23;
        float4 hv = *(const float4*)&g_hA[aa];
        float4 ev = *(const float4*)&se[cls * 64 + ch4];
        accA.x = fmaf(ex, hv.x + ev.x, accA.x);
        accA.y = fmaf(ex, hv.y + ev.y, accA.y);
        accA.z = fmaf(ex, hv.z + ev.z, accA.z);
        accA.w = fmaf(ex, hv.w + ev.w, accA.w);
    }

    accA.x += accB.x; accA.y += accB.y; accA.z += accB.z; accA.w += accB.w;
    accA.x += __shfl_xor_sync(0xffffffffu, accA.x, 16);
    accA.y += __shfl_xor_sync(0xffffffffu, accA.y, 16);
    accA.z += __shfl_xor_sync(0xffffffffu, accA.z, 16);
    accA.w += __shfl_xor_sync(0xffffffffu, accA.w, 16);

    if (half == 0) {
        const float* b = bias + l * 64 + ch4;
        float4 o;
        o.x = fmaf(accA.x, inv, b[0]);
        o.y = fmaf(accA.y, inv, b[1]);
        o.z = fmaf(accA.z, inv, b[2]);
        o.w = fmaf(accA.w, inv, b[3]);
        // ELU via fast exp: |err| ~1e-7 for our O(0.3) inputs
        o.x = o.x > 0.f ? o.x : __expf(o.x) - 1.f;
        o.y = o.y > 0.f ? o.y : __expf(o.y) - 1.f;
        o.z = o.z > 0.f ? o.z : __expf(o.z) - 1.f;
        o.w = o.w > 0.f ? o.w : __expf(o.w) - 1.f;
        *(float4*)&g_hB[n * 64 + ch4] = o;
    }
}

// ---------------- 64x64 GEMM with f32x2 packed FMA ----------------
// smem loaded directly as 64-bit pairs (no per-element packing movs).
__global__ __launch_bounds__(256) void k_gemm(const float* __restrict__ W13,
                                              const float* __restrict__ asrc,
                                              const float* __restrict__ adst, int l) {
    __shared__ __align__(16) float Wsf[4096];   // W[k][j]
    __shared__ float Hs[128 * 33];
    __shared__ float Av[64], Dv[64];

    int t = threadIdx.x;
    const float* W = W13 + (l - 1) * 4096;
    for (int i = t; i < 4096; i += 256) Wsf[i] = W[i];
    if (t < 64) { Av[t] = asrc[l * 64 + t]; Dv[t] = adst[l * 64 + t]; }

    int base = blockIdx.x * 128;
    int rows = NN - base; if (rows > 128) rows = 128;
    int node_l = t >> 1, h = t & 1;

    ull acc2[16];
    #pragma unroll
    for (int j = 0; j < 16; j++) acc2[j] = 0ull;

    for (int ph = 0; ph < 2; ph++) {
        __syncthreads();
        for (int i = t; i < rows * 32; i += 256) {
            int r = i >> 5, kk = i & 31;
            Hs[r * 33 + kk] = g_hB[(base + r) * 64 + ph * 32 + kk];
        }
        __syncthreads();
        if (node_l < rows) {
            #pragma unroll 4
            for (int kk = 0; kk < 32; kk++) {
                float rk = Hs[node_l * 33 + kk];
                ull rk2 = pk2(rk, rk);
                int k = ph * 32 + kk;
                const ULL2* wr = (const ULL2*)&Wsf[k * 64 + h * 32];  // 16B-aligned
                #pragma unroll
                for (int j4 = 0; j4 < 8; j4++) {
                    ULL2 w = wr[j4];                 // LDS.128 -> two reg pairs
                    acc2[2 * j4]     = fma2(rk2, w.a, acc2[2 * j4]);
                    acc2[2 * j4 + 1] = fma2(rk2, w.b, acc2[2 * j4 + 1]);
                }
            }
        }
    }

    if (node_l < rows) {
        int n = base + node_l;
        float accf[32];
        #pragma unroll
        for (int j = 0; j < 16; j++) {
            float2 v = upk2(acc2[j]);
            accf[2 * j] = v.x;
            accf[2 * j + 1] = v.y;
        }
        float ss = 0.f, sdd = 0.f;
        #pragma unroll
        for (int j = 0; j < 32; j++) {
            ss  = fmaf(accf[j], Av[h * 32 + j], ss);
            sdd = fmaf(accf[j], Dv[h * 32 + j], sdd);
        }
        float4* op = (float4*)&g_hA[n * 64 + h * 32];
        #pragma unroll
        for (int j4 = 0; j4 < 8; j4++)
            op[j4] = make_float4(accf[4 * j4], accf[4 * j4 + 1],
                                 accf[4 * j4 + 2], accf[4 * j4 + 3]);
        g_ssrc[2 * n + h] = ss;
        g_sdst[2 * n + h] = sdd;
    }
}

// ---------------- MF decoder ----------------
__global__ void k_decode(float* __restrict__ out) {
    int t = threadIdx.x, warp = t >> 5, lane = t & 31;
    int i = blockIdx.x * 8 + warp;
    if (i >= 25000) return;
    const float2* u = (const float2*)&g_hB[(4 * i) * 64];
    const float2* v = (const float2*)&g_hB[(4 * i + 1) * 64];
    float2 a = u[lane], b = v[lane];
    float s = a.x * b.x + a.y * b.y;
    #pragma unroll
    for (int o = 16; o; o >>= 1) s += __shfl_xor_sync(0xffffffffu, s, o);
    if (lane == 0) out[i] = s;
}

// ---------------- launch ----------------
extern "C" void kernel_launch(void* const* d_in, const int* in_sizes, int n_in,
                              void* d_out, int out_size) {
    const float* W0   = (const float*)d_in[1];
    const float* W13  = (const float*)d_in[2];
    const float* eemb = (const float*)d_in[3];
    const float* asrc = (const float*)d_in[4];
    const float* adst = (const float*)d_in[5];
    const float* bias = (const float*)d_in[6];
    const int*   ei   = (const int*)d_in[7];
    const int*   ea   = (const int*)d_in[8];
    float* out = (float*)d_out;

    void* degp; cudaGetSymbolAddress(&degp, g_deg);
    void* tickp; cudaGetSymbolAddress(&tickp, g_ticket);
    cudaMemsetAsync(degp, 0, NN * sizeof(int));
    cudaMemsetAsync(tickp, 0, sizeof(int));

    k_count_deg<<<(EE + 255) / 256, 256>>>(ei);                              // 1
    k_scan<<<(NN + 1023) / 1024, 1024>>>();                                  // 2
    k_scatter_fill<<<(EE + 255) / 256, 256>>>(ei, ea, W0, eemb, asrc, adst); // 3
    k_edge<<<NN / 8, 256>>>(eemb, bias, 0);                                  // 4 <- profiled
    for (int l = 1; l < 4; l++) {
        k_gemm<<<(NN + 127) / 128, 256>>>(W13, asrc, adst, l);
        k_edge<<<NN / 8, 256>>>(eemb, bias, l);
    }
    k_decode<<<(25000 + 7) / 8, 256>>>(out);
}